// round 14
// baseline (speedup 1.0000x reference)
#include <cuda_runtime.h>
#include <cuda_bf16.h>
#include <math.h>

#define NB 2
#define NC 4
#define NL 1024
#define NF 256
#define NH 8
#define ND 32
#define NN (NB*NL)
#define NBH (NB*NC*NH)
#define HOUT_SIZE (NB*NC*NL*NF)

typedef unsigned int u32;

__device__ __forceinline__ void mma16816(float* c, const u32* a, const u32* b) {
    asm volatile("mma.sync.aligned.m16n8k16.row.col.f32.bf16.bf16.f32 "
        "{%0,%1,%2,%3}, {%4,%5,%6,%7}, {%8,%9}, {%0,%1,%2,%3};"
        : "+f"(c[0]), "+f"(c[1]), "+f"(c[2]), "+f"(c[3])
        : "r"(a[0]), "r"(a[1]), "r"(a[2]), "r"(a[3]), "r"(b[0]), "r"(b[1]));
}
__device__ __forceinline__ u32 pk2h(__nv_bfloat16 a, __nv_bfloat16 b) {
    unsigned short ua = *(unsigned short*)&a, ub = *(unsigned short*)&b;
    return (u32)ua | ((u32)ub << 16);
}
__device__ __forceinline__ u32 s2u(const void* p) {
    return (u32)__cvta_generic_to_shared(p);
}
__device__ __forceinline__ void ldsm4(u32& r0, u32& r1, u32& r2, u32& r3, u32 addr) {
    asm volatile("ldmatrix.sync.aligned.m8n8.x4.shared.b16 {%0,%1,%2,%3}, [%4];"
        : "=r"(r0), "=r"(r1), "=r"(r2), "=r"(r3) : "r"(addr));
}
__device__ __forceinline__ void cpa16(u32 dst, const void* src) {
    asm volatile("cp.async.cg.shared.global [%0], [%1], 16;" :: "r"(dst), "l"(src));
}
__device__ __forceinline__ void cpa_commit() {
    asm volatile("cp.async.commit_group;");
}

__device__ __forceinline__ void split2(float p0, float p1, u32& hi, u32& lo) {
    float2 pf = make_float2(p0, p1);
    __nv_bfloat162 h = __float22bfloat162_rn(pf);
    float2 hf = __bfloat1622float2(h);
    __nv_bfloat162 l = __float22bfloat162_rn(make_float2(p0 - hf.x, p1 - hf.y));
    hi = *(u32*)&h;
    lo = *(u32*)&l;
}

// ------------------- scratch (bf16 hi/lo interchange) -------------------
__device__ __nv_bfloat16 g_convh[12*NN*NF], g_convl[12*NN*NF];
__device__ __nv_bfloat16 g_wh[16*65536],    g_wl[16*65536];
__device__ __nv_bfloat16 g_qh_h[NBH*NL*ND], g_qh_l[NBH*NL*ND];
__device__ __nv_bfloat16 g_kh_h[NBH*NL*ND], g_kh_l[NBH*NL*ND];
__device__ __nv_bfloat16 g_vT_h[NBH*ND*NL], g_vT_l[NBH*ND*NL];
__device__ __nv_bfloat16 g_ah[NC*NN*NF],    g_al[NC*NN*NF];
__device__ float g_o[NC*NN*NF];
__device__ float g_rcos[NL*16], g_rsin[NL*16];

// =================================================================================
// Kernel 1 (fused): norm+conv / weight split / rope
// =================================================================================
__global__ void __launch_bounds__(256) k_nc_prep(
    const float* __restrict__ x,
    const float* __restrict__ g1, const float* __restrict__ b1,
    const float* __restrict__ wqc, const float* __restrict__ wkc, const float* __restrict__ wvc,
    const float* __restrict__ wq, const float* __restrict__ wk,
    const float* __restrict__ wv, const float* __restrict__ wo)
{
    int bidx = blockIdx.x;
    int f = threadIdx.x;

    if (bidx >= 2048) {
        if (bidx < 6144) {
            int idx = (bidx - 2048)*256 + f;
            int mat = idx >> 18, rem = idx & 262143;
            const float* src = (mat == 0) ? wq : (mat == 1) ? wk : (mat == 2) ? wv : wo;
            float v = src[rem];
            __nv_bfloat16 h = __float2bfloat16(v);
            g_wh[idx] = h;
            g_wl[idx] = __float2bfloat16(v - __bfloat162float(h));
        } else {
            int idx = (bidx - 6144)*256 + f;
            if (idx < NL*16) {
                int l = idx >> 4, i = idx & 15;
                float inv = powf(10000.f, -(float)i / 16.f);
                float s, c;
                sincosf((float)l * inv, &s, &c);
                g_rcos[idx] = c;
                g_rsin[idx] = s;
            }
        }
        return;
    }

    __shared__ float snx[4][256];
    __shared__ float sw[3][4][4][3];
    __shared__ float sA[4][8], sB[4][8];

    int n = bidx;
    int b = n >> 10, l = n & 1023;
    int wid = f >> 5, lane = f & 31;

    if (f < 144) {
        int mat = f / 48, rem = f % 48;
        int o = rem / 12, i = (rem % 12) / 3, kh = rem % 3;
        const float* wsrc = (mat == 0) ? wqc : (mat == 1) ? wkc : wvc;
        sw[mat][o][i][kh] = wsrc[(o*4 + i)*9 + kh*3 + 1];
    }

    float xv[4];
    #pragma unroll
    for (int c = 0; c < 4; c++)
        xv[c] = x[((size_t)(b*4 + c)*1024 + l)*256 + f];

    #pragma unroll
    for (int c = 0; c < 4; c++) {
        float v = xv[c], v2 = v*v;
        #pragma unroll
        for (int off = 16; off; off >>= 1) {
            v  += __shfl_xor_sync(0xffffffffu, v,  off);
            v2 += __shfl_xor_sync(0xffffffffu, v2, off);
        }
        if (lane == 0) { sA[c][wid] = v; sB[c][wid] = v2; }
    }
    __syncthreads();

    #pragma unroll
    for (int c = 0; c < 4; c++) {
        float s = 0.f, ss = 0.f;
        #pragma unroll
        for (int w = 0; w < 8; w++) { s += sA[c][w]; ss += sB[c][w]; }
        float mean = s * (1.f/256.f);
        float var  = ss * (1.f/256.f) - mean*mean;
        snx[c][f] = (xv[c] - mean) * rsqrtf(var + 1e-5f) * g1[c] + b1[c];
    }
    __syncthreads();

    float le[4], ce[4], ri[4];
    #pragma unroll
    for (int i = 0; i < 4; i++) {
        le[i] = (f > 0)   ? snx[i][f-1] : 0.f;
        ce[i] = snx[i][f];
        ri[i] = (f < 255) ? snx[i][f+1] : 0.f;
    }
    #pragma unroll
    for (int mat = 0; mat < 3; mat++) {
        #pragma unroll
        for (int o = 0; o < 4; o++) {
            float acc = 0.f;
            #pragma unroll
            for (int i = 0; i < 4; i++)
                acc += le[i]*sw[mat][o][i][0] + ce[i]*sw[mat][o][i][1] + ri[i]*sw[mat][o][i][2];
            size_t oi = ((size_t)(mat*4 + o)*NN + n)*256 + f;
            __nv_bfloat16 h = __float2bfloat16(acc);
            g_convh[oi] = h;
            g_convl[oi] = __float2bfloat16(acc - __bfloat162float(h));
        }
    }
}

// =================================================================================
// Kernel 2/4: split-bf16 mma GEMM with 2-stage cp.async pipeline, 2 blocks/SM
// =================================================================================
#define GSTG (128*40)

__global__ void __launch_bounds__(256, 2) k_gemm_mma(int phase)
{
    extern __shared__ __nv_bfloat16 smem[];
    __nv_bfloat16* sXh = smem;
    __nv_bfloat16* sXl = smem + 2*GSTG;
    __nv_bfloat16* sWh = smem + 4*GSTG;
    __nv_bfloat16* sWl = smem + 6*GSTG;

    int t = threadIdx.x, w = t >> 5, lane = t & 31;
    int g = lane >> 2, q = lane & 3;
    int wr = w >> 2, wc = w & 3;
    int n0 = blockIdx.x * 128, g0 = blockIdx.y * 128, z = blockIdx.z;

    const __nv_bfloat16 *Ah, *Al, *Wh, *Wl;
    int mat, c;
    if (phase == 0) {
        mat = z >> 2; c = z & 3;
        Ah = g_convh + (size_t)z*NN*NF;  Al = g_convl + (size_t)z*NN*NF;
        Wh = g_wh + (size_t)z*65536;     Wl = g_wl + (size_t)z*65536;
    } else {
        mat = 3; c = z;
        Ah = g_ah + (size_t)c*NN*NF;     Al = g_al + (size_t)c*NN*NF;
        Wh = g_wh + (size_t)(12 + c)*65536; Wl = g_wl + (size_t)(12 + c)*65536;
    }

    u32 bXh = s2u(sXh), bXl = s2u(sXl), bWh = s2u(sWh), bWl = s2u(sWl);

    int lr0 = t >> 2, lg0 = t & 3;
    #define LOAD_CHUNK(cidx, stg) { \
        int k0_ = (cidx)*32; \
        u32 so_ = (u32)((stg)*GSTG*2); \
        _Pragma("unroll") \
        for (int j = 0; j < 2; j++) { \
            int row = lr0 + j*64, sg = lg0; \
            u32 d_ = (u32)((row*40 + sg*8)*2) + so_; \
            size_t ga = (size_t)(n0 + row)*256 + k0_ + sg*8; \
            size_t gb = (size_t)(g0 + row)*256 + k0_ + sg*8; \
            cpa16(bXh + d_, &Ah[ga]); \
            cpa16(bXl + d_, &Al[ga]); \
            cpa16(bWh + d_, &Wh[gb]); \
            cpa16(bWl + d_, &Wl[gb]); \
        } \
        cpa_commit(); }

    int laneA = (lane & 15)*40 + (lane >> 4)*8;
    int laneB = (((lane & 16) >> 1) + (lane & 7))*40 + ((lane & 8) ? 8 : 0);
    int mrb = wr*64, ncb = wc*32;

    float acc[4][4][4];
    #pragma unroll
    for (int i = 0; i < 4; i++)
        #pragma unroll
        for (int j = 0; j < 4; j++)
            #pragma unroll
            for (int k = 0; k < 4; k++) acc[i][j][k] = 0.f;

    LOAD_CHUNK(0, 0);

    for (int cix = 0; cix < 8; cix++) {
        int s = cix & 1;
        if (cix < 7) {
            LOAD_CHUNK(cix + 1, s ^ 1);
            asm volatile("cp.async.wait_group 1;");
        } else {
            asm volatile("cp.async.wait_group 0;");
        }
        __syncthreads();

        u32 soff = (u32)(s*GSTG*2);
        #pragma unroll
        for (int ks = 0; ks < 2; ks++) {
            int kk = ks*16;
            u32 bhr[4][2], blr[4][2];
            #pragma unroll
            for (int nf2 = 0; nf2 < 2; nf2++) {
                u32 off = (u32)(((ncb + nf2*16)*40 + kk + laneB) * 2) + soff;
                ldsm4(bhr[2*nf2][0], bhr[2*nf2][1], bhr[2*nf2+1][0], bhr[2*nf2+1][1], bWh + off);
                ldsm4(blr[2*nf2][0], blr[2*nf2][1], blr[2*nf2+1][0], blr[2*nf2+1][1], bWl + off);
            }
            #pragma unroll
            for (int mf = 0; mf < 4; mf++) {
                u32 off = (u32)(((mrb + mf*16)*40 + kk + laneA) * 2) + soff;
                u32 ah[4], al[4];
                ldsm4(ah[0], ah[1], ah[2], ah[3], bXh + off);
                ldsm4(al[0], al[1], al[2], al[3], bXl + off);
                #pragma unroll
                for (int nf = 0; nf < 4; nf++) {
                    mma16816(acc[mf][nf], ah, bhr[nf]);
                    mma16816(acc[mf][nf], al, bhr[nf]);
                    mma16816(acc[mf][nf], ah, blr[nf]);
                }
            }
        }
        __syncthreads();
    }

    if (phase == 1) {
        float* outp = g_o + (size_t)c*NN*NF;
        #pragma unroll
        for (int mf = 0; mf < 4; mf++) {
            #pragma unroll
            for (int rr = 0; rr < 2; rr++) {
                int n = n0 + mrb + mf*16 + g + rr*8;
                #pragma unroll
                for (int nf = 0; nf < 4; nf++) {
                    int gc = g0 + ncb + nf*8 + 2*q;
                    *(float2*)&outp[(size_t)n*256 + gc] =
                        make_float2(acc[mf][nf][2*rr], acc[mf][nf][2*rr+1]);
                }
            }
        }
    } else {
        #pragma unroll
        for (int mf = 0; mf < 4; mf++) {
            #pragma unroll
            for (int rr = 0; rr < 2; rr++) {
                int n = n0 + mrb + mf*16 + g + rr*8;
                int b = n >> 10, l = n & 1023;
                #pragma unroll
                for (int nf = 0; nf < 4; nf++) {
                    int gc = g0 + ncb + nf*8 + 2*q;
                    float v0 = acc[mf][nf][2*rr], v1 = acc[mf][nf][2*rr+1];
                    if (mat < 2) {
                        int i0 = (gc & 31) >> 1;
                        float cs = g_rcos[l*16 + i0], sn = g_rsin[l*16 + i0];
                        float r0 = v0*cs - v1*sn;
                        float r1 = v1*cs + v0*sn;
                        v0 = r0; v1 = r1;
                        if (mat == 0) { v0 *= 0.0625f; v1 *= 0.0625f; }
                    }
                    int h = gc >> 5, d = gc & 31;
                    int bh = (b*4 + c)*8 + h;
                    u32 hiw, low;
                    split2(v0, v1, hiw, low);
                    if (mat == 0) {
                        size_t o = ((size_t)bh*1024 + l)*32 + d;
                        *(u32*)&g_qh_h[o] = hiw;
                        *(u32*)&g_qh_l[o] = low;
                    } else if (mat == 1) {
                        size_t o = ((size_t)bh*1024 + l)*32 + d;
                        *(u32*)&g_kh_h[o] = hiw;
                        *(u32*)&g_kh_l[o] = low;
                    } else {
                        size_t o = ((size_t)bh*32 + d)*1024 + l;
                        __nv_bfloat162 hh = *(__nv_bfloat162*)&hiw;
                        __nv_bfloat162 ll = *(__nv_bfloat162*)&low;
                        g_vT_h[o] = hh.x; g_vT_h[o + 1024] = hh.y;
                        g_vT_l[o] = ll.x; g_vT_l[o + 1024] = ll.y;
                    }
                }
            }
        }
    }
}

// =================================================================================
// Kernel 3: flash attention, single-pass (R8/R9 structure) with 3-stage KV pipeline.
// =================================================================================
#define AT_QT   5120
#define AT_STG  9728
#define AT_SMEM ((10240 + 3*AT_STG)*2)   // 78848 bytes

__global__ void __launch_bounds__(256, 2) k_attn(
    const float* __restrict__ prev_qk, float* __restrict__ qk_out)
{
    extern __shared__ __nv_bfloat16 sm[];
    __nv_bfloat16* sQh = sm;
    __nv_bfloat16* sQl = sm + AT_QT;

    int t = threadIdx.x, w = t >> 5, lane = t & 31;
    int g = lane >> 2, q = lane & 3;
    int bh = blockIdx.y;
    int l0 = blockIdx.x * 128;

    const __nv_bfloat16* Qh = g_qh_h + (size_t)bh*NL*ND;
    const __nv_bfloat16* Ql = g_qh_l + (size_t)bh*NL*ND;
    const __nv_bfloat16* Kh = g_kh_h + (size_t)bh*NL*ND;
    const __nv_bfloat16* Kl = g_kh_l + (size_t)bh*NL*ND;
    const __nv_bfloat16* Vh = g_vT_h + (size_t)bh*ND*NL;
    const __nv_bfloat16* Vl = g_vT_l + (size_t)bh*ND*NL;
    const float* Pp  = prev_qk + (size_t)bh*NL*NL;
    float*       QKo = qk_out  + (size_t)bh*NL*NL;

    #pragma unroll
    for (int j = 0; j < 2; j++) {
        int idx = t + 256*j;
        int row = idx >> 2, sg = idx & 3;
        size_t so = (size_t)(l0 + row)*32 + sg*8;
        *(uint4*)&sQh[row*40 + sg*8] = *(const uint4*)&Qh[so];
        *(uint4*)&sQl[row*40 + sg*8] = *(const uint4*)&Ql[so];
    }

    u32 stgB = s2u(sm + 10240);
    int krow = t >> 2, ksg = t & 3;
    int vd   = t >> 3, vsg = t & 7;

    #define AT_LOAD(m0_, s_) { \
        u32 sb = stgB + (u32)(s_)*(AT_STG*2); \
        u32 kd = (u32)((krow*40 + ksg*8)*2); \
        cpa16(sb + kd,            &Kh[(size_t)((m0_) + krow)*32 + ksg*8]); \
        cpa16(sb + 5120 + kd,     &Kl[(size_t)((m0_) + krow)*32 + ksg*8]); \
        u32 vdd = (u32)((vd*72 + vsg*8)*2); \
        cpa16(sb + 10240 + vdd,   &Vh[(size_t)vd*NL + (m0_) + vsg*8]); \
        cpa16(sb + 14848 + vdd,   &Vl[(size_t)vd*NL + (m0_) + vsg*8]); \
        cpa_commit(); }

    int laneA  = (lane & 15)*40 + (lane >> 4)*8;
    int laneBK = (((lane & 16) >> 1) + (lane & 7))*40 + ((lane & 8) ? 8 : 0);
    int laneBV = (((lane & 16) >> 1) + (lane & 7))*72 + ((lane & 8) ? 8 : 0);
    u32 bQh = s2u(sQh), bQl = s2u(sQl);

    float O[4][4];
    #pragma unroll
    for (int i = 0; i < 4; i++)
        #pragma unroll
        for (int j = 0; j < 4; j++) O[i][j] = 0.f;
    float M0 = -1e30f, M1 = -1e30f, S0 = 0.f, S1 = 0.f;
    int rowA = 16*w + g;

    AT_LOAD(0, 0);
    AT_LOAD(64, 1);

    int s = 0;       // compute stage
    int ls = 2;      // next load stage
    for (int it = 0; it < 16; it++) {
        int m0 = it*64;

        // prev_qk register prefetch (DRAM, consumed after QK mma)
        float2 pv[8][2];
        #pragma unroll
        for (int nf = 0; nf < 8; nf++) {
            #pragma unroll
            for (int rr = 0; rr < 2; rr++) {
                size_t off = (size_t)(l0 + rowA + rr*8)*NL + m0 + nf*8 + 2*q;
                pv[nf][rr] = *(const float2*)&Pp[off];
            }
        }

        if (it < 14) {
            AT_LOAD(m0 + 128, ls);
            asm volatile("cp.async.wait_group 2;");
        } else if (it == 14) {
            asm volatile("cp.async.wait_group 1;");
        } else {
            asm volatile("cp.async.wait_group 0;");
        }
        __syncthreads();

        u32 sb  = stgB + (u32)s*(AT_STG*2);
        u32 bKh = sb, bKl = sb + 5120, bVh = sb + 10240, bVl = sb + 14848;

        float qk[8][4];
        #pragma unroll
        for (int nf = 0; nf < 8; nf++)
            #pragma unroll
            for (int i = 0; i < 4; i++) qk[nf][i] = 0.f;

        #pragma unroll
        for (int ks = 0; ks < 2; ks++) {
            int kk = ks*16;
            u32 aoff = (u32)(((16*w)*40 + kk + laneA) * 2);
            u32 ah[4], al[4];
            ldsm4(ah[0], ah[1], ah[2], ah[3], bQh + aoff);
            ldsm4(al[0], al[1], al[2], al[3], bQl + aoff);
            #pragma unroll
            for (int nf2 = 0; nf2 < 4; nf2++) {
                u32 boff = (u32)(((nf2*16)*40 + kk + laneBK) * 2);
                u32 kb[4], kbl[4];
                ldsm4(kb[0], kb[1], kb[2], kb[3], bKh + boff);
                ldsm4(kbl[0], kbl[1], kbl[2], kbl[3], bKl + boff);
                mma16816(qk[2*nf2],   ah, kb);
                mma16816(qk[2*nf2],   al, kb);
                mma16816(qk[2*nf2],   ah, kbl);
                mma16816(qk[2*nf2+1], ah, kb + 2);
                mma16816(qk[2*nf2+1], al, kb + 2);
                mma16816(qk[2*nf2+1], ah, kbl + 2);
            }
        }

        float lm0 = -1e30f, lm1 = -1e30f;
        #pragma unroll
        for (int nf = 0; nf < 8; nf++) {
            qk[nf][0] += pv[nf][0].x; qk[nf][1] += pv[nf][0].y;
            qk[nf][2] += pv[nf][1].x; qk[nf][3] += pv[nf][1].y;
            size_t off0 = (size_t)(l0 + rowA    )*NL + m0 + nf*8 + 2*q;
            size_t off1 = (size_t)(l0 + rowA + 8)*NL + m0 + nf*8 + 2*q;
            *(float2*)&QKo[off0] = make_float2(qk[nf][0], qk[nf][1]);
            *(float2*)&QKo[off1] = make_float2(qk[nf][2], qk[nf][3]);
            lm0 = fmaxf(lm0, fmaxf(qk[nf][0], qk[nf][1]));
            lm1 = fmaxf(lm1, fmaxf(qk[nf][2], qk[nf][3]));
        }
        lm0 = fmaxf(lm0, __shfl_xor_sync(0xffffffffu, lm0, 1));
        lm0 = fmaxf(lm0, __shfl_xor_sync(0xffffffffu, lm0, 2));
        lm1 = fmaxf(lm1, __shfl_xor_sync(0xffffffffu, lm1, 1));
        lm1 = fmaxf(lm1, __shfl_xor_sync(0xffffffffu, lm1, 2));

        float nm0 = fmaxf(M0, lm0), nm1 = fmaxf(M1, lm1);
        float sc0 = __expf(M0 - nm0), sc1 = __expf(M1 - nm1);
        M0 = nm0; M1 = nm1;

        u32 ph01[8], ph23[8], pl01[8], pl23[8];
        float ls0 = 0.f, ls1 = 0.f;
        #pragma unroll
        for (int nf = 0; nf < 8; nf++) {
            float p0 = __expf(qk[nf][0] - nm0);
            float p1 = __expf(qk[nf][1] - nm0);
            float p2 = __expf(qk[nf][2] - nm1);
            float p3 = __expf(qk[nf][3] - nm1);
            ls0 += p0 + p1; ls1 += p2 + p3;
            __nv_bfloat16 h0 = __float2bfloat16(p0);
            __nv_bfloat16 h1 = __float2bfloat16(p1);
            __nv_bfloat16 h2 = __float2bfloat16(p2);
            __nv_bfloat16 h3 = __float2bfloat16(p3);
            ph01[nf] = pk2h(h0, h1);
            ph23[nf] = pk2h(h2, h3);
            pl01[nf] = pk2h(__float2bfloat16(p0 - __bfloat162float(h0)),
                            __float2bfloat16(p1 - __bfloat162float(h1)));
            pl23[nf] = pk2h(__float2bfloat16(p2 - __bfloat162float(h2)),
                            __float2bfloat16(p3 - __bfloat162float(h3)));
        }
        S0 = S0*sc0 + ls0;
        S1 = S1*sc1 + ls1;
        #pragma unroll
        for (int nf2 = 0; nf2 < 4; nf2++) {
            O[nf2][0] *= sc0; O[nf2][1] *= sc0;
            O[nf2][2] *= sc1; O[nf2][3] *= sc1;
        }

        #pragma unroll
        for (int ks2 = 0; ks2 < 4; ks2++) {
            u32 pa[4]  = { ph01[2*ks2], ph23[2*ks2], ph01[2*ks2+1], ph23[2*ks2+1] };
            u32 pla[4] = { pl01[2*ks2], pl23[2*ks2], pl01[2*ks2+1], pl23[2*ks2+1] };
            #pragma unroll
            for (int p2i = 0; p2i < 2; p2i++) {
                u32 voff = (u32)(((p2i*16)*72 + ks2*16 + laneBV) * 2);
                u32 vb[4], vlb[4];
                ldsm4(vb[0], vb[1], vb[2], vb[3], bVh + voff);
                ldsm4(vlb[0], vlb[1], vlb[2], vlb[3], bVl + voff);
                mma16816(O[2*p2i],   pa,  vb);
                mma16816(O[2*p2i],   pla, vb);
                mma16816(O[2*p2i],   pa,  vlb);
                mma16816(O[2*p2i+1], pa,  vb + 2);
                mma16816(O[2*p2i+1], pla, vb + 2);
                mma16816(O[2*p2i+1], pa,  vlb + 2);
            }
        }
        __syncthreads();   // stage s free for reload at it+3

        s  = (s  == 2) ? 0 : s + 1;
        ls = (ls == 2) ? 0 : ls + 1;
    }

    S0 += __shfl_xor_sync(0xffffffffu, S0, 1);
    S0 += __shfl_xor_sync(0xffffffffu, S0, 2);
    S1 += __shfl_xor_sync(0xffffffffu, S1, 1);
    S1 += __shfl_xor_sync(0xffffffffu, S1, 2);
    float inv0 = 1.f / S0, inv1 = 1.f / S1;

    int b = bh >> 5;
    int c = (bh >> 3) & 3;
    int h = bh & 7;
    int n0r = b*1024 + l0 + rowA;
    #pragma unroll
    for (int nf2 = 0; nf2 < 4; nf2++) {
        int col = h*32 + nf2*8 + 2*q;
        float v0 = O[nf2][0]*inv0, v1 = O[nf2][1]*inv0;
        float v2 = O[nf2][2]*inv1, v3 = O[nf2][3]*inv1;
        size_t o0 = ((size_t)c*NN + n0r    )*256 + col;
        size_t o1 = ((size_t)c*NN + n0r + 8)*256 + col;
        u32 hiw, low;
        split2(v0, v1, hiw, low);
        *(u32*)&g_ah[o0] = hiw;
        *(u32*)&g_al[o0] = low;
        split2(v2, v3, hiw, low);
        *(u32*)&g_ah[o1] = hiw;
        *(u32*)&g_al[o1] = low;
    }
}

// =================================================================================
// Kernel 5: FFN tail
// =================================================================================
__global__ void __launch_bounds__(256) k_ffn(
    const float* __restrict__ x,
    const float* __restrict__ g2, const float* __restrict__ b2,
    const float* __restrict__ w1, const float* __restrict__ w2,
    const float* __restrict__ dw, float* __restrict__ hout)
{
    __shared__ float sz[8][256];
    __shared__ float sz1[8][4];
    __shared__ float sA[8][8], sB[8][8];

    int f = threadIdx.x;
    int n = blockIdx.x;
    int b = n >> 10, l = n & 1023;
    int wid = f >> 5, lane = f & 31;

    float zv[8];
    #pragma unroll
    for (int c = 0; c < 4; c++) {
        zv[c]     = x[((size_t)(b*4 + c)*1024 + l)*256 + f];
        zv[4 + c] = g_o[((size_t)c*NN + n)*256 + f];
    }

    #pragma unroll
    for (int ch = 0; ch < 8; ch++) {
        float v = zv[ch], v2 = v*v;
        #pragma unroll
        for (int off = 16; off; off >>= 1) {
            v  += __shfl_xor_sync(0xffffffffu, v,  off);
            v2 += __shfl_xor_sync(0xffffffffu, v2, off);
        }
        if (lane == 0) { sA[ch][wid] = v; sB[ch][wid] = v2; }
    }
    __syncthreads();

    #pragma unroll
    for (int ch = 0; ch < 8; ch++) {
        float s = 0.f, ss = 0.f;
        #pragma unroll
        for (int w = 0; w < 8; w++) { s += sA[ch][w]; ss += sB[ch][w]; }
        float mean = s * (1.f/256.f);
        float var  = ss * (1.f/256.f) - mean*mean;
        sz[ch][f] = (zv[ch] - mean) * rsqrtf(var + 1e-5f) * g2[ch] + b2[ch];
    }
    __syncthreads();

    float a0 = 0.f, a1 = 0.f, a2 = 0.f, a3 = 0.f;
    #pragma unroll
    for (int k = 0; k < 8; k++) {
        int ff = lane + 32*k;
        float zf = sz[wid][ff];
        a0 += zf * w1[(wid*4 + 0)*256 + ff];
        a1 += zf * w1[(wid*4 + 1)*256 + ff];
        a2 += zf * w1[(wid*4 + 2)*256 + ff];
        a3 += zf * w1[(wid*4 + 3)*256 + ff];
    }
    #pragma unroll
    for (int off = 16; off; off >>= 1) {
        a0 += __shfl_xor_sync(0xffffffffu, a0, off);
        a1 += __shfl_xor_sync(0xffffffffu, a1, off);
        a2 += __shfl_xor_sync(0xffffffffu, a2, off);
        a3 += __shfl_xor_sync(0xffffffffu, a3, off);
    }
    if (lane == 0) {
        sz1[wid][0] = (a0 > 0.f) ? a0 : 0.01f*a0;
        sz1[wid][1] = (a1 > 0.f) ? a1 : 0.01f*a1;
        sz1[wid][2] = (a2 > 0.f) ? a2 : 0.01f*a2;
        sz1[wid][3] = (a3 > 0.f) ? a3 : 0.01f*a3;
    }
    __syncthreads();

    float ho[4] = {0.f, 0.f, 0.f, 0.f};
    #pragma unroll
    for (int c = 0; c < 8; c++) {
        float4 wv = *(const float4*)&w2[((size_t)c*256 + f)*4];
        float z2 = sz1[c][0]*wv.x + sz1[c][1]*wv.y + sz1[c][2]*wv.z + sz1[c][3]*wv.w;
        #pragma unroll
        for (int d = 0; d < 4; d++)
            ho[d] += z2 * dw[d*8 + c];
    }
    #pragma unroll
    for (int d = 0; d < 4; d++) {
        size_t idx = ((size_t)(b*4 + d)*1024 + l)*256 + f;
        hout[idx] = x[idx] + ho[d];
    }
}

// =================================================================================
extern "C" void kernel_launch(void* const* d_in, const int* in_sizes, int n_in,
                              void* d_out, int out_size)
{
    const float* x       = (const float*)d_in[0];
    const float* prev_qk = (const float*)d_in[1];
    const float* g1      = (const float*)d_in[2];
    const float* b1      = (const float*)d_in[3];
    const float* wq_conv = (const float*)d_in[4];
    const float* wk_conv = (const float*)d_in[5];
    const float* wv_conv = (const float*)d_in[6];
    const float* wq_pw   = (const float*)d_in[7];
    const float* wk_pw   = (const float*)d_in[8];
    const float* wv_pw   = (const float*)d_in[9];
    const float* wo_pw   = (const float*)d_in[10];
    const float* g2      = (const float*)d_in[11];
    const float* b2      = (const float*)d_in[12];
    const float* w1_pw   = (const float*)d_in[13];
    const float* w2_pw   = (const float*)d_in[14];
    const float* w2_dw   = (const float*)d_in[15];

    float* out  = (float*)d_out;
    float* qk_o = out + HOUT_SIZE;

    static int attr_set = 0;
    if (!attr_set) {
        cudaFuncSetAttribute(k_gemm_mma, cudaFuncAttributeMaxDynamicSharedMemorySize,
                             8*GSTG*sizeof(__nv_bfloat16));
        cudaFuncSetAttribute(k_attn, cudaFuncAttributeMaxDynamicSharedMemorySize,
                             AT_SMEM);
        attr_set = 1;
    }

    k_nc_prep<<<6208, 256>>>(x, g1, b1, wq_conv, wk_conv, wv_conv,
                             wq_pw, wk_pw, wv_pw, wo_pw);
    k_gemm_mma<<<dim3(16, 2, 12), 256, 8*GSTG*sizeof(__nv_bfloat16)>>>(0);
    k_attn<<<dim3(8, NBH), 256, AT_SMEM>>>(prev_qk, qk_o);
    k_gemm_mma<<<dim3(16, 2, 4), 256, 8*GSTG*sizeof(__nv_bfloat16)>>>(1);
    k_ffn<<<NN, 256>>>(x, g2, b2, w1_pw, w2_pw, w2_dw, out);
}

// round 15
// speedup vs baseline: 1.0803x; 1.0803x over previous
#include <cuda_runtime.h>
#include <cuda_bf16.h>
#include <math.h>

#define NB 2
#define NC 4
#define NL 1024
#define NF 256
#define NH 8
#define ND 32
#define NN (NB*NL)
#define NBH (NB*NC*NH)
#define HOUT_SIZE (NB*NC*NL*NF)

typedef unsigned int u32;

__device__ __forceinline__ void mma16816(float* c, const u32* a, const u32* b) {
    asm volatile("mma.sync.aligned.m16n8k16.row.col.f32.bf16.bf16.f32 "
        "{%0,%1,%2,%3}, {%4,%5,%6,%7}, {%8,%9}, {%0,%1,%2,%3};"
        : "+f"(c[0]), "+f"(c[1]), "+f"(c[2]), "+f"(c[3])
        : "r"(a[0]), "r"(a[1]), "r"(a[2]), "r"(a[3]), "r"(b[0]), "r"(b[1]));
}
__device__ __forceinline__ u32 pk2h(__nv_bfloat16 a, __nv_bfloat16 b) {
    unsigned short ua = *(unsigned short*)&a, ub = *(unsigned short*)&b;
    return (u32)ua | ((u32)ub << 16);
}
__device__ __forceinline__ u32 s2u(const void* p) {
    return (u32)__cvta_generic_to_shared(p);
}
__device__ __forceinline__ void ldsm4(u32& r0, u32& r1, u32& r2, u32& r3, u32 addr) {
    asm volatile("ldmatrix.sync.aligned.m8n8.x4.shared.b16 {%0,%1,%2,%3}, [%4];"
        : "=r"(r0), "=r"(r1), "=r"(r2), "=r"(r3) : "r"(addr));
}
__device__ __forceinline__ void cpa16(u32 dst, const void* src) {
    asm volatile("cp.async.cg.shared.global [%0], [%1], 16;" :: "r"(dst), "l"(src));
}
__device__ __forceinline__ void cpa_commit() {
    asm volatile("cp.async.commit_group;");
}

// split a float2 into bf16x2 hi + bf16x2 lo (vectorized cvt)
__device__ __forceinline__ void split2(float p0, float p1, u32& hi, u32& lo) {
    float2 pf = make_float2(p0, p1);
    __nv_bfloat162 h = __float22bfloat162_rn(pf);
    float2 hf = __bfloat1622float2(h);
    __nv_bfloat162 l = __float22bfloat162_rn(make_float2(p0 - hf.x, p1 - hf.y));
    hi = *(u32*)&h;
    lo = *(u32*)&l;
}

// ------------------- scratch (bf16 hi/lo interchange) -------------------
__device__ __nv_bfloat16 g_convh[12*NN*NF], g_convl[12*NN*NF];
__device__ __nv_bfloat16 g_wh[16*65536],    g_wl[16*65536];
__device__ __nv_bfloat16 g_qh_h[NBH*NL*ND], g_qh_l[NBH*NL*ND];
__device__ __nv_bfloat16 g_kh_h[NBH*NL*ND], g_kh_l[NBH*NL*ND];
__device__ __nv_bfloat16 g_vT_h[NBH*ND*NL], g_vT_l[NBH*ND*NL];
__device__ __nv_bfloat16 g_ah[NC*NN*NF],    g_al[NC*NN*NF];
__device__ float g_o[NC*NN*NF];
__device__ float g_rcos[NL*16], g_rsin[NL*16];

// =================================================================================
// Kernel 1 (fused): norm+conv / weight split / rope
// =================================================================================
__global__ void __launch_bounds__(256) k_nc_prep(
    const float* __restrict__ x,
    const float* __restrict__ g1, const float* __restrict__ b1,
    const float* __restrict__ wqc, const float* __restrict__ wkc, const float* __restrict__ wvc,
    const float* __restrict__ wq, const float* __restrict__ wk,
    const float* __restrict__ wv, const float* __restrict__ wo)
{
    int bidx = blockIdx.x;
    int f = threadIdx.x;

    if (bidx >= 2048) {
        if (bidx < 6144) {
            int idx = (bidx - 2048)*256 + f;
            int mat = idx >> 18, rem = idx & 262143;
            const float* src = (mat == 0) ? wq : (mat == 1) ? wk : (mat == 2) ? wv : wo;
            float v = src[rem];
            __nv_bfloat16 h = __float2bfloat16(v);
            g_wh[idx] = h;
            g_wl[idx] = __float2bfloat16(v - __bfloat162float(h));
        } else {
            int idx = (bidx - 6144)*256 + f;
            if (idx < NL*16) {
                int l = idx >> 4, i = idx & 15;
                float inv = powf(10000.f, -(float)i / 16.f);
                float s, c;
                sincosf((float)l * inv, &s, &c);
                g_rcos[idx] = c;
                g_rsin[idx] = s;
            }
        }
        return;
    }

    __shared__ float snx[4][256];
    __shared__ float sw[3][4][4][3];
    __shared__ float sA[4][8], sB[4][8];

    int n = bidx;
    int b = n >> 10, l = n & 1023;
    int wid = f >> 5, lane = f & 31;

    if (f < 144) {
        int mat = f / 48, rem = f % 48;
        int o = rem / 12, i = (rem % 12) / 3, kh = rem % 3;
        const float* wsrc = (mat == 0) ? wqc : (mat == 1) ? wkc : wvc;
        sw[mat][o][i][kh] = wsrc[(o*4 + i)*9 + kh*3 + 1];
    }

    float xv[4];
    #pragma unroll
    for (int c = 0; c < 4; c++)
        xv[c] = x[((size_t)(b*4 + c)*1024 + l)*256 + f];

    #pragma unroll
    for (int c = 0; c < 4; c++) {
        float v = xv[c], v2 = v*v;
        #pragma unroll
        for (int off = 16; off; off >>= 1) {
            v  += __shfl_xor_sync(0xffffffffu, v,  off);
            v2 += __shfl_xor_sync(0xffffffffu, v2, off);
        }
        if (lane == 0) { sA[c][wid] = v; sB[c][wid] = v2; }
    }
    __syncthreads();

    #pragma unroll
    for (int c = 0; c < 4; c++) {
        float s = 0.f, ss = 0.f;
        #pragma unroll
        for (int w = 0; w < 8; w++) { s += sA[c][w]; ss += sB[c][w]; }
        float mean = s * (1.f/256.f);
        float var  = ss * (1.f/256.f) - mean*mean;
        snx[c][f] = (xv[c] - mean) * rsqrtf(var + 1e-5f) * g1[c] + b1[c];
    }
    __syncthreads();

    float le[4], ce[4], ri[4];
    #pragma unroll
    for (int i = 0; i < 4; i++) {
        le[i] = (f > 0)   ? snx[i][f-1] : 0.f;
        ce[i] = snx[i][f];
        ri[i] = (f < 255) ? snx[i][f+1] : 0.f;
    }
    #pragma unroll
    for (int mat = 0; mat < 3; mat++) {
        #pragma unroll
        for (int o = 0; o < 4; o++) {
            float acc = 0.f;
            #pragma unroll
            for (int i = 0; i < 4; i++)
                acc += le[i]*sw[mat][o][i][0] + ce[i]*sw[mat][o][i][1] + ri[i]*sw[mat][o][i][2];
            size_t oi = ((size_t)(mat*4 + o)*NN + n)*256 + f;
            __nv_bfloat16 h = __float2bfloat16(acc);
            g_convh[oi] = h;
            g_convl[oi] = __float2bfloat16(acc - __bfloat162float(h));
        }
    }
}

// =================================================================================
// Kernel 2/4: split-bf16 mma GEMM with 2-stage cp.async pipeline, 2 blocks/SM
// =================================================================================
#define GSTG (128*40)

__global__ void __launch_bounds__(256, 2) k_gemm_mma(int phase)
{
    extern __shared__ __nv_bfloat16 smem[];
    __nv_bfloat16* sXh = smem;
    __nv_bfloat16* sXl = smem + 2*GSTG;
    __nv_bfloat16* sWh = smem + 4*GSTG;
    __nv_bfloat16* sWl = smem + 6*GSTG;

    int t = threadIdx.x, w = t >> 5, lane = t & 31;
    int g = lane >> 2, q = lane & 3;
    int wr = w >> 2, wc = w & 3;
    int n0 = blockIdx.x * 128, g0 = blockIdx.y * 128, z = blockIdx.z;

    const __nv_bfloat16 *Ah, *Al, *Wh, *Wl;
    int mat, c;
    if (phase == 0) {
        mat = z >> 2; c = z & 3;
        Ah = g_convh + (size_t)z*NN*NF;  Al = g_convl + (size_t)z*NN*NF;
        Wh = g_wh + (size_t)z*65536;     Wl = g_wl + (size_t)z*65536;
    } else {
        mat = 3; c = z;
        Ah = g_ah + (size_t)c*NN*NF;     Al = g_al + (size_t)c*NN*NF;
        Wh = g_wh + (size_t)(12 + c)*65536; Wl = g_wl + (size_t)(12 + c)*65536;
    }

    u32 bXh = s2u(sXh), bXl = s2u(sXl), bWh = s2u(sWh), bWl = s2u(sWl);

    int lr0 = t >> 2, lg0 = t & 3;
    #define LOAD_CHUNK(cidx, stg) { \
        int k0_ = (cidx)*32; \
        u32 so_ = (u32)((stg)*GSTG*2); \
        _Pragma("unroll") \
        for (int j = 0; j < 2; j++) { \
            int row = lr0 + j*64, sg = lg0; \
            u32 d_ = (u32)((row*40 + sg*8)*2) + so_; \
            size_t ga = (size_t)(n0 + row)*256 + k0_ + sg*8; \
            size_t gb = (size_t)(g0 + row)*256 + k0_ + sg*8; \
            cpa16(bXh + d_, &Ah[ga]); \
            cpa16(bXl + d_, &Al[ga]); \
            cpa16(bWh + d_, &Wh[gb]); \
            cpa16(bWl + d_, &Wl[gb]); \
        } \
        cpa_commit(); }

    int laneA = (lane & 15)*40 + (lane >> 4)*8;
    int laneB = (((lane & 16) >> 1) + (lane & 7))*40 + ((lane & 8) ? 8 : 0);
    int mrb = wr*64, ncb = wc*32;

    float acc[4][4][4];
    #pragma unroll
    for (int i = 0; i < 4; i++)
        #pragma unroll
        for (int j = 0; j < 4; j++)
            #pragma unroll
            for (int k = 0; k < 4; k++) acc[i][j][k] = 0.f;

    LOAD_CHUNK(0, 0);

    for (int cix = 0; cix < 8; cix++) {
        int s = cix & 1;
        if (cix < 7) {
            LOAD_CHUNK(cix + 1, s ^ 1);
            asm volatile("cp.async.wait_group 1;");
        } else {
            asm volatile("cp.async.wait_group 0;");
        }
        __syncthreads();

        u32 soff = (u32)(s*GSTG*2);
        #pragma unroll
        for (int ks = 0; ks < 2; ks++) {
            int kk = ks*16;
            u32 bhr[4][2], blr[4][2];
            #pragma unroll
            for (int nf2 = 0; nf2 < 2; nf2++) {
                u32 off = (u32)(((ncb + nf2*16)*40 + kk + laneB) * 2) + soff;
                ldsm4(bhr[2*nf2][0], bhr[2*nf2][1], bhr[2*nf2+1][0], bhr[2*nf2+1][1], bWh + off);
                ldsm4(blr[2*nf2][0], blr[2*nf2][1], blr[2*nf2+1][0], blr[2*nf2+1][1], bWl + off);
            }
            #pragma unroll
            for (int mf = 0; mf < 4; mf++) {
                u32 off = (u32)(((mrb + mf*16)*40 + kk + laneA) * 2) + soff;
                u32 ah[4], al[4];
                ldsm4(ah[0], ah[1], ah[2], ah[3], bXh + off);
                ldsm4(al[0], al[1], al[2], al[3], bXl + off);
                #pragma unroll
                for (int nf = 0; nf < 4; nf++) {
                    mma16816(acc[mf][nf], ah, bhr[nf]);
                    mma16816(acc[mf][nf], al, bhr[nf]);
                    mma16816(acc[mf][nf], ah, blr[nf]);
                }
            }
        }
        __syncthreads();
    }

    if (phase == 1) {
        float* outp = g_o + (size_t)c*NN*NF;
        #pragma unroll
        for (int mf = 0; mf < 4; mf++) {
            #pragma unroll
            for (int rr = 0; rr < 2; rr++) {
                int n = n0 + mrb + mf*16 + g + rr*8;
                #pragma unroll
                for (int nf = 0; nf < 4; nf++) {
                    int gc = g0 + ncb + nf*8 + 2*q;
                    *(float2*)&outp[(size_t)n*256 + gc] =
                        make_float2(acc[mf][nf][2*rr], acc[mf][nf][2*rr+1]);
                }
            }
        }
    } else {
        #pragma unroll
        for (int mf = 0; mf < 4; mf++) {
            #pragma unroll
            for (int rr = 0; rr < 2; rr++) {
                int n = n0 + mrb + mf*16 + g + rr*8;
                int b = n >> 10, l = n & 1023;
                #pragma unroll
                for (int nf = 0; nf < 4; nf++) {
                    int gc = g0 + ncb + nf*8 + 2*q;
                    float v0 = acc[mf][nf][2*rr], v1 = acc[mf][nf][2*rr+1];
                    if (mat < 2) {
                        int i0 = (gc & 31) >> 1;
                        float cs = g_rcos[l*16 + i0], sn = g_rsin[l*16 + i0];
                        float r0 = v0*cs - v1*sn;
                        float r1 = v1*cs + v0*sn;
                        v0 = r0; v1 = r1;
                        if (mat == 0) { v0 *= 0.0625f; v1 *= 0.0625f; }
                    }
                    int h = gc >> 5, d = gc & 31;
                    int bh = (b*4 + c)*8 + h;
                    u32 hiw, low;
                    split2(v0, v1, hiw, low);
                    if (mat == 0) {
                        size_t o = ((size_t)bh*1024 + l)*32 + d;
                        *(u32*)&g_qh_h[o] = hiw;
                        *(u32*)&g_qh_l[o] = low;
                    } else if (mat == 1) {
                        size_t o = ((size_t)bh*1024 + l)*32 + d;
                        *(u32*)&g_kh_h[o] = hiw;
                        *(u32*)&g_kh_l[o] = low;
                    } else {
                        size_t o = ((size_t)bh*32 + d)*1024 + l;
                        __nv_bfloat162 hh = *(__nv_bfloat162*)&hiw;
                        __nv_bfloat162 ll = *(__nv_bfloat162*)&low;
                        g_vT_h[o] = hh.x; g_vT_h[o + 1024] = hh.y;
                        g_vT_l[o] = ll.x; g_vT_l[o + 1024] = ll.y;
                    }
                }
            }
        }
    }
}

// =================================================================================
// Kernel 3: flash attention (R8 best structure: pv registers, 2-stage KV pipeline)
// + streaming cache hints on the prev_qk/qk DRAM streams.
// =================================================================================
#define AT_QT   5120
#define AT_STG  9728
#define AT_SMEM ((10240 + 2*AT_STG)*2)

__global__ void __launch_bounds__(256, 2) k_attn(
    const float* __restrict__ prev_qk, float* __restrict__ qk_out)
{
    extern __shared__ __nv_bfloat16 sm[];
    __nv_bfloat16* sQh = sm;
    __nv_bfloat16* sQl = sm + AT_QT;

    int t = threadIdx.x, w = t >> 5, lane = t & 31;
    int g = lane >> 2, q = lane & 3;
    int bh = blockIdx.y;
    int l0 = blockIdx.x * 128;

    const __nv_bfloat16* Qh = g_qh_h + (size_t)bh*NL*ND;
    const __nv_bfloat16* Ql = g_qh_l + (size_t)bh*NL*ND;
    const __nv_bfloat16* Kh = g_kh_h + (size_t)bh*NL*ND;
    const __nv_bfloat16* Kl = g_kh_l + (size_t)bh*NL*ND;
    const __nv_bfloat16* Vh = g_vT_h + (size_t)bh*ND*NL;
    const __nv_bfloat16* Vl = g_vT_l + (size_t)bh*ND*NL;
    const float* Pp  = prev_qk + (size_t)bh*NL*NL;
    float*       QKo = qk_out  + (size_t)bh*NL*NL;

    #pragma unroll
    for (int j = 0; j < 2; j++) {
        int idx = t + 256*j;
        int row = idx >> 2, sg = idx & 3;
        size_t so = (size_t)(l0 + row)*32 + sg*8;
        *(uint4*)&sQh[row*40 + sg*8] = *(const uint4*)&Qh[so];
        *(uint4*)&sQl[row*40 + sg*8] = *(const uint4*)&Ql[so];
    }

    u32 stgB = s2u(sm + 10240);
    int krow = t >> 2, ksg = t & 3;
    int vd   = t >> 3, vsg = t & 7;

    #define AT_LOAD(m0_, s_) { \
        u32 sb = stgB + (u32)(s_)*(AT_STG*2); \
        u32 kd = (u32)((krow*40 + ksg*8)*2); \
        cpa16(sb + kd,            &Kh[(size_t)((m0_) + krow)*32 + ksg*8]); \
        cpa16(sb + 5120 + kd,     &Kl[(size_t)((m0_) + krow)*32 + ksg*8]); \
        u32 vdd = (u32)((vd*72 + vsg*8)*2); \
        cpa16(sb + 10240 + vdd,   &Vh[(size_t)vd*NL + (m0_) + vsg*8]); \
        cpa16(sb + 14848 + vdd,   &Vl[(size_t)vd*NL + (m0_) + vsg*8]); \
        cpa_commit(); }

    int laneA  = (lane & 15)*40 + (lane >> 4)*8;
    int laneBK = (((lane & 16) >> 1) + (lane & 7))*40 + ((lane & 8) ? 8 : 0);
    int laneBV = (((lane & 16) >> 1) + (lane & 7))*72 + ((lane & 8) ? 8 : 0);
    u32 bQh = s2u(sQh), bQl = s2u(sQl);

    float O[4][4];
    #pragma unroll
    for (int i = 0; i < 4; i++)
        #pragma unroll
        for (int j = 0; j < 4; j++) O[i][j] = 0.f;
    float M0 = -1e30f, M1 = -1e30f, S0 = 0.f, S1 = 0.f;
    int rowA = 16*w + g;

    AT_LOAD(0, 0);

    for (int it = 0; it < 16; it++) {
        int m0 = it*64;
        int s = it & 1;

        // prev_qk register prefetch (streaming: read-once, evict-first)
        float2 pv[8][2];
        #pragma unroll
        for (int nf = 0; nf < 8; nf++) {
            #pragma unroll
            for (int rr = 0; rr < 2; rr++) {
                size_t off = (size_t)(l0 + rowA + rr*8)*NL + m0 + nf*8 + 2*q;
                pv[nf][rr] = __ldcs((const float2*)&Pp[off]);
            }
        }

        if (it < 15) {
            AT_LOAD(m0 + 64, s ^ 1);
            asm volatile("cp.async.wait_group 1;");
        } else {
            asm volatile("cp.async.wait_group 0;");
        }
        __syncthreads();

        u32 sb  = stgB + (u32)s*(AT_STG*2);
        u32 bKh = sb, bKl = sb + 5120, bVh = sb + 10240, bVl = sb + 14848;

        float qk[8][4];
        #pragma unroll
        for (int nf = 0; nf < 8; nf++)
            #pragma unroll
            for (int i = 0; i < 4; i++) qk[nf][i] = 0.f;

        #pragma unroll
        for (int ks = 0; ks < 2; ks++) {
            int kk = ks*16;
            u32 aoff = (u32)(((16*w)*40 + kk + laneA) * 2);
            u32 ah[4], al[4];
            ldsm4(ah[0], ah[1], ah[2], ah[3], bQh + aoff);
            ldsm4(al[0], al[1], al[2], al[3], bQl + aoff);
            #pragma unroll
            for (int nf2 = 0; nf2 < 4; nf2++) {
                u32 boff = (u32)(((nf2*16)*40 + kk + laneBK) * 2);
                u32 kb[4], kbl[4];
                ldsm4(kb[0], kb[1], kb[2], kb[3], bKh + boff);
                ldsm4(kbl[0], kbl[1], kbl[2], kbl[3], bKl + boff);
                mma16816(qk[2*nf2],   ah, kb);
                mma16816(qk[2*nf2],   al, kb);
                mma16816(qk[2*nf2],   ah, kbl);
                mma16816(qk[2*nf2+1], ah, kb + 2);
                mma16816(qk[2*nf2+1], al, kb + 2);
                mma16816(qk[2*nf2+1], ah, kbl + 2);
            }
        }

        float lm0 = -1e30f, lm1 = -1e30f;
        #pragma unroll
        for (int nf = 0; nf < 8; nf++) {
            qk[nf][0] += pv[nf][0].x; qk[nf][1] += pv[nf][0].y;
            qk[nf][2] += pv[nf][1].x; qk[nf][3] += pv[nf][1].y;
            size_t off0 = (size_t)(l0 + rowA    )*NL + m0 + nf*8 + 2*q;
            size_t off1 = (size_t)(l0 + rowA + 8)*NL + m0 + nf*8 + 2*q;
            __stcs((float2*)&QKo[off0], make_float2(qk[nf][0], qk[nf][1]));
            __stcs((float2*)&QKo[off1], make_float2(qk[nf][2], qk[nf][3]));
            lm0 = fmaxf(lm0, fmaxf(qk[nf][0], qk[nf][1]));
            lm1 = fmaxf(lm1, fmaxf(qk[nf][2], qk[nf][3]));
        }
        lm0 = fmaxf(lm0, __shfl_xor_sync(0xffffffffu, lm0, 1));
        lm0 = fmaxf(lm0, __shfl_xor_sync(0xffffffffu, lm0, 2));
        lm1 = fmaxf(lm1, __shfl_xor_sync(0xffffffffu, lm1, 1));
        lm1 = fmaxf(lm1, __shfl_xor_sync(0xffffffffu, lm1, 2));

        float nm0 = fmaxf(M0, lm0), nm1 = fmaxf(M1, lm1);
        float sc0 = __expf(M0 - nm0), sc1 = __expf(M1 - nm1);
        M0 = nm0; M1 = nm1;

        u32 ph01[8], ph23[8], pl01[8], pl23[8];
        float ls0 = 0.f, ls1 = 0.f;
        #pragma unroll
        for (int nf = 0; nf < 8; nf++) {
            float p0 = __expf(qk[nf][0] - nm0);
            float p1 = __expf(qk[nf][1] - nm0);
            float p2 = __expf(qk[nf][2] - nm1);
            float p3 = __expf(qk[nf][3] - nm1);
            ls0 += p0 + p1; ls1 += p2 + p3;
            __nv_bfloat16 h0 = __float2bfloat16(p0);
            __nv_bfloat16 h1 = __float2bfloat16(p1);
            __nv_bfloat16 h2 = __float2bfloat16(p2);
            __nv_bfloat16 h3 = __float2bfloat16(p3);
            ph01[nf] = pk2h(h0, h1);
            ph23[nf] = pk2h(h2, h3);
            pl01[nf] = pk2h(__float2bfloat16(p0 - __bfloat162float(h0)),
                            __float2bfloat16(p1 - __bfloat162float(h1)));
            pl23[nf] = pk2h(__float2bfloat16(p2 - __bfloat162float(h2)),
                            __float2bfloat16(p3 - __bfloat162float(h3)));
        }
        S0 = S0*sc0 + ls0;
        S1 = S1*sc1 + ls1;
        #pragma unroll
        for (int nf2 = 0; nf2 < 4; nf2++) {
            O[nf2][0] *= sc0; O[nf2][1] *= sc0;
            O[nf2][2] *= sc1; O[nf2][3] *= sc1;
        }

        #pragma unroll
        for (int ks2 = 0; ks2 < 4; ks2++) {
            u32 pa[4]  = { ph01[2*ks2], ph23[2*ks2], ph01[2*ks2+1], ph23[2*ks2+1] };
            u32 pla[4] = { pl01[2*ks2], pl23[2*ks2], pl01[2*ks2+1], pl23[2*ks2+1] };
            #pragma unroll
            for (int p2i = 0; p2i < 2; p2i++) {
                u32 voff = (u32)(((p2i*16)*72 + ks2*16 + laneBV) * 2);
                u32 vb[4], vlb[4];
                ldsm4(vb[0], vb[1], vb[2], vb[3], bVh + voff);
                ldsm4(vlb[0], vlb[1], vlb[2], vlb[3], bVl + voff);
                mma16816(O[2*p2i],   pa,  vb);
                mma16816(O[2*p2i],   pla, vb);
                mma16816(O[2*p2i],   pa,  vlb);
                mma16816(O[2*p2i+1], pa,  vb + 2);
                mma16816(O[2*p2i+1], pla, vb + 2);
                mma16816(O[2*p2i+1], pa,  vlb + 2);
            }
        }
        __syncthreads();
    }

    S0 += __shfl_xor_sync(0xffffffffu, S0, 1);
    S0 += __shfl_xor_sync(0xffffffffu, S0, 2);
    S1 += __shfl_xor_sync(0xffffffffu, S1, 1);
    S1 += __shfl_xor_sync(0xffffffffu, S1, 2);
    float inv0 = 1.f / S0, inv1 = 1.f / S1;

    int b = bh >> 5;
    int c = (bh >> 3) & 3;
    int h = bh & 7;
    int n0r = b*1024 + l0 + rowA;
    #pragma unroll
    for (int nf2 = 0; nf2 < 4; nf2++) {
        int col = h*32 + nf2*8 + 2*q;
        float v0 = O[nf2][0]*inv0, v1 = O[nf2][1]*inv0;
        float v2 = O[nf2][2]*inv1, v3 = O[nf2][3]*inv1;
        size_t o0 = ((size_t)c*NN + n0r    )*256 + col;
        size_t o1 = ((size_t)c*NN + n0r + 8)*256 + col;
        u32 hiw, low;
        split2(v0, v1, hiw, low);
        *(u32*)&g_ah[o0] = hiw;
        *(u32*)&g_al[o0] = low;
        split2(v2, v3, hiw, low);
        *(u32*)&g_ah[o1] = hiw;
        *(u32*)&g_al[o1] = low;
    }
}

// =================================================================================
// Kernel 5: FFN tail (residual reuses loaded x values)
// =================================================================================
__global__ void __launch_bounds__(256) k_ffn(
    const float* __restrict__ x,
    const float* __restrict__ g2, const float* __restrict__ b2,
    const float* __restrict__ w1, const float* __restrict__ w2,
    const float* __restrict__ dw, float* __restrict__ hout)
{
    __shared__ float sz[8][256];
    __shared__ float sz1[8][4];
    __shared__ float sA[8][8], sB[8][8];

    int f = threadIdx.x;
    int n = blockIdx.x;
    int b = n >> 10, l = n & 1023;
    int wid = f >> 5, lane = f & 31;

    float zv[8];
    #pragma unroll
    for (int c = 0; c < 4; c++) {
        zv[c]     = x[((size_t)(b*4 + c)*1024 + l)*256 + f];
        zv[4 + c] = g_o[((size_t)c*NN + n)*256 + f];
    }

    #pragma unroll
    for (int ch = 0; ch < 8; ch++) {
        float v = zv[ch], v2 = v*v;
        #pragma unroll
        for (int off = 16; off; off >>= 1) {
            v  += __shfl_xor_sync(0xffffffffu, v,  off);
            v2 += __shfl_xor_sync(0xffffffffu, v2, off);
        }
        if (lane == 0) { sA[ch][wid] = v; sB[ch][wid] = v2; }
    }
    __syncthreads();

    #pragma unroll
    for (int ch = 0; ch < 8; ch++) {
        float s = 0.f, ss = 0.f;
        #pragma unroll
        for (int w = 0; w < 8; w++) { s += sA[ch][w]; ss += sB[ch][w]; }
        float mean = s * (1.f/256.f);
        float var  = ss * (1.f/256.f) - mean*mean;
        sz[ch][f] = (zv[ch] - mean) * rsqrtf(var + 1e-5f) * g2[ch] + b2[ch];
    }
    __syncthreads();

    float a0 = 0.f, a1 = 0.f, a2 = 0.f, a3 = 0.f;
    #pragma unroll
    for (int k = 0; k < 8; k++) {
        int ff = lane + 32*k;
        float zf = sz[wid][ff];
        a0 += zf * w1[(wid*4 + 0)*256 + ff];
        a1 += zf * w1[(wid*4 + 1)*256 + ff];
        a2 += zf * w1[(wid*4 + 2)*256 + ff];
        a3 += zf * w1[(wid*4 + 3)*256 + ff];
    }
    #pragma unroll
    for (int off = 16; off; off >>= 1) {
        a0 += __shfl_xor_sync(0xffffffffu, a0, off);
        a1 += __shfl_xor_sync(0xffffffffu, a1, off);
        a2 += __shfl_xor_sync(0xffffffffu, a2, off);
        a3 += __shfl_xor_sync(0xffffffffu, a3, off);
    }
    if (lane == 0) {
        sz1[wid][0] = (a0 > 0.f) ? a0 : 0.01f*a0;
        sz1[wid][1] = (a1 > 0.f) ? a1 : 0.01f*a1;
        sz1[wid][2] = (a2 > 0.f) ? a2 : 0.01f*a2;
        sz1[wid][3] = (a3 > 0.f) ? a3 : 0.01f*a3;
    }
    __syncthreads();

    float ho[4] = {0.f, 0.f, 0.f, 0.f};
    #pragma unroll
    for (int c = 0; c < 8; c++) {
        float4 wv = *(const float4*)&w2[((size_t)c*256 + f)*4];
        float z2 = sz1[c][0]*wv.x + sz1[c][1]*wv.y + sz1[c][2]*wv.z + sz1[c][3]*wv.w;
        #pragma unroll
        for (int d = 0; d < 4; d++)
            ho[d] += z2 * dw[d*8 + c];
    }
    #pragma unroll
    for (int d = 0; d < 4; d++) {
        size_t idx = ((size_t)(b*4 + d)*1024 + l)*256 + f;
        hout[idx] = zv[d] + ho[d];   // zv[d] holds x for channel d (reuse, no reload)
    }
}

// =================================================================================
extern "C" void kernel_launch(void* const* d_in, const int* in_sizes, int n_in,
                              void* d_out, int out_size)
{
    const float* x       = (const float*)d_in[0];
    const float* prev_qk = (const float*)d_in[1];
    const float* g1      = (const float*)d_in[2];
    const float* b1      = (const float*)d_in[3];
    const float* wq_conv = (const float*)d_in[4];
    const float* wk_conv = (const float*)d_in[5];
    const float* wv_conv = (const float*)d_in[6];
    const float* wq_pw   = (const float*)d_in[7];
    const float* wk_pw   = (const float*)d_in[8];
    const float* wv_pw   = (const float*)d_in[9];
    const float* wo_pw   = (const float*)d_in[10];
    const float* g2      = (const float*)d_in[11];
    const float* b2      = (const float*)d_in[12];
    const float* w1_pw   = (const float*)d_in[13];
    const float* w2_pw   = (const float*)d_in[14];
    const float* w2_dw   = (const float*)d_in[15];

    float* out  = (float*)d_out;
    float* qk_o = out + HOUT_SIZE;

    static int attr_set = 0;
    if (!attr_set) {
        cudaFuncSetAttribute(k_gemm_mma, cudaFuncAttributeMaxDynamicSharedMemorySize,
                             8*GSTG*sizeof(__nv_bfloat16));
        cudaFuncSetAttribute(k_attn, cudaFuncAttributeMaxDynamicSharedMemorySize,
                             AT_SMEM);
        attr_set = 1;
    }

    k_nc_prep<<<6208, 256>>>(x, g1, b1, wq_conv, wk_conv, wv_conv,
                             wq_pw, wk_pw, wv_pw, wo_pw);
    k_gemm_mma<<<dim3(16, 2, 12), 256, 8*GSTG*sizeof(__nv_bfloat16)>>>(0);
    k_attn<<<dim3(8, NBH), 256, AT_SMEM>>>(prev_qk, qk_o);
    k_gemm_mma<<<dim3(16, 2, 4), 256, 8*GSTG*sizeof(__nv_bfloat16)>>>(1);
    k_ffn<<<NN, 256>>>(x, g2, b2, w1_pw, w2_pw, w2_dw, out);
}